// round 10
// baseline (speedup 1.0000x reference)
#include <cuda_runtime.h>
#include <cuda_fp16.h>
#include <cstdint>

// ---------------------------------------------------------------------------
// Problem constants
// ---------------------------------------------------------------------------
#define THREADS 256
#define F_DIM 160
#define NQ 4096
#define NA 32768
#define NC 10
#define SPLITS 32
#define A_CHUNK 1024          // addresses per CTA
#define TN 64                 // N tile (addresses per tile)
#define NTILES (A_CHUNK / TN) // 16
#define KEXP (-1.31154095f)   // -log2(e)/1.1 : exp(-d/1.1) = 2^(d*KEXP)
#define WSHIFT 24.0f          // softmin-invariant weight scale 2^24
#define TCLAMP 14.0f          // clamp t -> w <= 2^14 (fp16-safe)

// ---------------------------------------------------------------------------
// Shared memory layout (fp16 tiles, 336B rows -> conflict-free ldmatrix).
// Mt and y2 are double-buffered for the software pipeline.
// ---------------------------------------------------------------------------
#define ROWB 336
#define MTROWB 144
#define OFF_X    0
#define SZ_X     (128 * ROWB)            // 43008
#define OFF_Y0   SZ_X                    // 43008
#define SZ_YBUF  (TN * ROWB)             // 21504
#define OFF_Y1   (OFF_Y0 + SZ_YBUF)      // 64512
#define OFF_MT0  (OFF_Y1 + SZ_YBUF)      // 86016
#define SZ_MTBUF (16 * MTROWB)           // 2304
#define OFF_MT1  (OFF_MT0 + SZ_MTBUF)    // 88320
#define OFF_Y2S0 (OFF_MT1 + SZ_MTBUF)    // 90624
#define OFF_Y2S1 (OFF_Y2S0 + 256)        // 90880
#define OFF_X2S  (OFF_Y2S1 + 256)        // 91136
#define SMEM_BYTES (OFF_X2S + 512)       // 91648  (1 CTA/SM)

// ---------------------------------------------------------------------------
// Device scratch
// ---------------------------------------------------------------------------
__device__ __half g_xh[(size_t)NQ * F_DIM];
__device__ __half g_yh[(size_t)NA * F_DIM];
__device__ float g_x2[NQ];
__device__ float g_y2[NA];
__device__ float g_part[(size_t)SPLITS * NQ * 16];  // [split][row][16]: 10 num, den@10

// ---------------------------------------------------------------------------
// PTX helpers
// ---------------------------------------------------------------------------
__device__ __forceinline__ uint32_t cvta_s(const void* p) {
    uint32_t r;
    asm("{ .reg .u64 t; cvta.to.shared.u64 t, %1; cvt.u32.u64 %0, t; }"
        : "=r"(r) : "l"(p));
    return r;
}

#define LDMX4(r, a)                                                            \
    asm volatile("ldmatrix.sync.aligned.m8n8.x4.shared.b16 {%0,%1,%2,%3}, [%4];" \
                 : "=r"((r)[0]), "=r"((r)[1]), "=r"((r)[2]), "=r"((r)[3])      \
                 : "r"(a))

#define MMA_F16(d, a, b0, b1)                                                  \
    asm volatile("mma.sync.aligned.m16n8k16.row.col.f32.f16.f16.f32 "          \
                 "{%0,%1,%2,%3},{%4,%5,%6,%7},{%8,%9},{%0,%1,%2,%3};"          \
                 : "+f"((d)[0]), "+f"((d)[1]), "+f"((d)[2]), "+f"((d)[3])      \
                 : "r"((a)[0]), "r"((a)[1]), "r"((a)[2]), "r"((a)[3]),         \
                   "r"(b0), "r"(b1))

#define CPASYNC16(d, s)                                                        \
    asm volatile("cp.async.cg.shared.global [%0], [%1], 16;" :: "r"(d), "l"(s))
#define CPCOMMIT() asm volatile("cp.async.commit_group;" ::: "memory")
#define CPWAIT1()  asm volatile("cp.async.wait_group 1;" ::: "memory")

// issue cp.async for one Y tile (fp16): rows [a0row, a0row+64), 320B/row
__device__ __forceinline__ void issue_y(int a0row, uint32_t dbase, int tid) {
    const char* gs = (const char*)(g_yh + (size_t)a0row * F_DIM);
    #pragma unroll
    for (int k = 0; k < 5; k++) {
        int i = k * THREADS + tid;        // 64 rows x 20 x 16B
        int r = i / 20, c = i - r * 20;
        CPASYNC16(dbase + r * ROWB + c * 16, gs + (size_t)r * 320 + c * 16);
    }
}

// two f32 scores -> fp16x2 softmin-weight pair (one GEMM-2 A-fragment reg)
__device__ __forceinline__ uint32_t wpair2(float s0, float s1, float x2v, float2 y2) {
    float d20 = fmaxf(fmaf(-2.f, s0, x2v + y2.x), 0.f);
    float d21 = fmaxf(fmaf(-2.f, s1, x2v + y2.y), 0.f);
    float d0, d1;
    asm("sqrt.approx.ftz.f32 %0, %1;" : "=f"(d0) : "f"(d20));
    asm("sqrt.approx.ftz.f32 %0, %1;" : "=f"(d1) : "f"(d21));
    float t0 = fminf(fmaf(KEXP, d0, WSHIFT), TCLAMP);
    float t1 = fminf(fmaf(KEXP, d1, WSHIFT), TCLAMP);
    __half2 th = __floats2half2_rn(t0, t1);
    uint32_t w;
    asm("ex2.approx.f16x2 %0, %1;" : "=r"(w) : "r"(*(uint32_t*)&th));
    return w;
}

// one epilogue piece: 4 wpair2 + 2 GEMM-2 MMAs for (j2, mf)
__device__ __forceinline__ void epi_piece(
    int j2, int mf,
    const float (&accO)[2][4][4], float (&acc2)[2][2][4],
    const float (&x2a)[4], const uint32_t* bm, float2 y2lo, float2 y2hi)
{
    uint32_t af[4];
    af[0] = wpair2(accO[mf][j2 * 2][0],     accO[mf][j2 * 2][1],     x2a[mf * 2],     y2lo);
    af[1] = wpair2(accO[mf][j2 * 2][2],     accO[mf][j2 * 2][3],     x2a[mf * 2 + 1], y2lo);
    af[2] = wpair2(accO[mf][j2 * 2 + 1][0], accO[mf][j2 * 2 + 1][1], x2a[mf * 2],     y2hi);
    af[3] = wpair2(accO[mf][j2 * 2 + 1][2], accO[mf][j2 * 2 + 1][3], x2a[mf * 2 + 1], y2hi);
    MMA_F16(acc2[mf][0], af, bm[0], bm[2]);
    MMA_F16(acc2[mf][1], af, bm[1], bm[3]);
}

// ---------------------------------------------------------------------------
// Kernel 0: exact fp32 row norms + fp16 conversion
// ---------------------------------------------------------------------------
__global__ void norms_kernel(const float* __restrict__ X, const float* __restrict__ Y) {
    int gw = (int)((blockIdx.x * blockDim.x + threadIdx.x) >> 5);
    int lane = threadIdx.x & 31;
    const float4* src;
    uint2* dsth;
    float* dst;
    if (gw < NQ) {
        src = (const float4*)(X + (size_t)gw * F_DIM);
        dsth = (uint2*)(g_xh + (size_t)gw * F_DIM); dst = g_x2 + gw;
    } else if (gw < NQ + NA) {
        int r = gw - NQ;
        src = (const float4*)(Y + (size_t)r * F_DIM);
        dsth = (uint2*)(g_yh + (size_t)r * F_DIM); dst = g_y2 + r;
    } else return;
    float s = 0.f;
    #pragma unroll
    for (int k = 0; k < 2; k++) {
        int j = lane + k * 32;
        if (k == 0 || j < 40) {
            float4 v = src[j];
            s = fmaf(v.x, v.x, s); s = fmaf(v.y, v.y, s);
            s = fmaf(v.z, v.z, s); s = fmaf(v.w, v.w, s);
            __half2 h0 = __floats2half2_rn(v.x, v.y);
            __half2 h1 = __floats2half2_rn(v.z, v.w);
            uint2 u;
            u.x = *(uint32_t*)&h0; u.y = *(uint32_t*)&h1;
            dsth[j] = u;
        }
    }
    #pragma unroll
    for (int o = 16; o > 0; o >>= 1) s += __shfl_xor_sync(0xFFFFFFFFu, s, o);
    if (lane == 0) *dst = s;
}

// ---------------------------------------------------------------------------
// Software-pipelined tile body: GEMM-1(t) instructions interleaved with
// epilogue(t-1) pieces so tensor and FMA/MUFU pipes run concurrently.
// ---------------------------------------------------------------------------
template<bool EPI>
__device__ __forceinline__ void tile_body(
    int t, int a_start, int tid, int nw, int tig, int lrow, int lcol,
    uint32_t sb, char* sm,
    const uint32_t (&aA)[2], const uint32_t (&bBo)[2], const float (&x2a)[4],
    float (&accN)[2][4][4], float (&accO)[2][4][4], float (&acc2)[2][2][4],
    const float* __restrict__ Mv)
{
    // prefetch M tile (64x10) + y2 chunk for tile t (consumed at publish)
    float mv[3];
    float y2v = 0.f;
    #pragma unroll
    for (int k = 0; k < 3; k++) {
        int i = k * THREADS + tid;
        if (i < TN * NC) {
            int j = i / 10, c = i - j * 10;
            mv[k] = Mv[(size_t)(a_start + t * TN + j) * NC + c];
        }
    }
    if (tid < TN) y2v = g_y2[a_start + t * TN + tid];

    CPWAIT1();              // Y buffer [t&1] complete
    __syncthreads();        // S1: Y visible, Mt[(t-1)&1] visible, bufs free

    #pragma unroll
    for (int mf = 0; mf < 2; mf++)
        #pragma unroll
        for (int nf = 0; nf < 4; nf++)
            #pragma unroll
            for (int q = 0; q < 4; q++) accN[mf][nf][q] = 0.f;

    const uint32_t yB = sb + OFF_Y0 + (t & 1) * SZ_YBUF;
    const int po = (t - 1) & 1;
    const uint32_t bMb = sb + OFF_MT0 + po * SZ_MTBUF + lrow * MTROWB + lcol;
    const char* y2s = sm + OFF_Y2S0 + po * 256;
    uint32_t bm0[4], bm1[4];
    float2 y2lo0, y2hi0, y2lo1, y2hi1;

    #pragma unroll
    for (int ks = 0; ks < 10; ks++) {
        uint32_t afr[2][4], bfr[2][4];
        LDMX4(afr[0], aA[0] + ks * 32);
        LDMX4(afr[1], aA[1] + ks * 32);
        LDMX4(bfr[0], yB + bBo[0] + ks * 32);
        LDMX4(bfr[1], yB + bBo[1] + ks * 32);
        #pragma unroll
        for (int mf = 0; mf < 2; mf++)
            #pragma unroll
            for (int p = 0; p < 2; p++) {
                MMA_F16(accN[mf][p * 2],     afr[mf], bfr[p][0], bfr[p][2]);
                MMA_F16(accN[mf][p * 2 + 1], afr[mf], bfr[p][1], bfr[p][3]);
            }
        if (EPI) {      // interleave epilogue(t-1) pieces between K-steps
            if (ks == 1) {
                LDMX4(bm0, bMb + (nw * 32) * 2);
                y2lo0 = *(const float2*)(y2s + (nw * 32 + tig * 2) * 4);
                y2hi0 = *(const float2*)(y2s + (nw * 32 + 8 + tig * 2) * 4);
            }
            if (ks == 2) epi_piece(0, 0, accO, acc2, x2a, bm0, y2lo0, y2hi0);
            if (ks == 3) epi_piece(0, 1, accO, acc2, x2a, bm0, y2lo0, y2hi0);
            if (ks == 4) {
                LDMX4(bm1, bMb + (nw * 32 + 16) * 2);
                y2lo1 = *(const float2*)(y2s + (nw * 32 + 16 + tig * 2) * 4);
                y2hi1 = *(const float2*)(y2s + (nw * 32 + 24 + tig * 2) * 4);
            }
            if (ks == 5) epi_piece(1, 0, accO, acc2, x2a, bm1, y2lo1, y2hi1);
            if (ks == 6) epi_piece(1, 1, accO, acc2, x2a, bm1, y2lo1, y2hi1);
        }
    }
    __syncthreads();        // S2: all warps done with Y[t&1] and Mt[po]
    if (t + 2 < NTILES)
        issue_y(a_start + (t + 2) * TN, sb + OFF_Y0 + (t & 1) * SZ_YBUF, tid);
    CPCOMMIT();             // one group per iteration (may be empty)

    // publish Mt(t) + y2(t) into buffer t&1 (read after next S1)
    {
        const int pn = t & 1;
        char* mtb = sm + OFF_MT0 + pn * SZ_MTBUF;
        #pragma unroll
        for (int k = 0; k < 3; k++) {
            int i = k * THREADS + tid;
            if (i < TN * NC) {
                int j = i / 10, c = i - j * 10;
                *(__half*)(mtb + c * MTROWB + j * 2) = __float2half_rn(mv[k]);
            }
        }
        if (tid < TN) *((float*)(sm + OFF_Y2S0 + pn * 256) + tid) = y2v;
    }
}

// ---------------------------------------------------------------------------
// Kernel 1: fused, software-pipelined. grid = 1024; 256 threads; 1 CTA/SM.
// ---------------------------------------------------------------------------
__global__ void __launch_bounds__(THREADS, 1) fused_kernel(
    const float* __restrict__ Mv)
{
    extern __shared__ __align__(1024) char sm[];
    const uint32_t sb = cvta_s(sm);
    const int tid  = threadIdx.x;
    const int lane = tid & 31, warp = tid >> 5;
    const int mw = warp >> 1, nw = warp & 1;
    const int g = lane >> 2, tig = lane & 3;
    const int m_tile = (int)blockIdx.x >> 5;
    const int split  = (int)blockIdx.x & (SPLITS - 1);
    const int a_start = split * A_CHUNK;

    // --- prologue: Y tiles 0,1 async; X tile; x2; Mt const rows ---------
    issue_y(a_start, sb + OFF_Y0, tid); CPCOMMIT();
    issue_y(a_start + TN, sb + OFF_Y1, tid); CPCOMMIT();
    {
        const char* xg = (const char*)(g_xh + (size_t)m_tile * 128 * F_DIM);
        #pragma unroll
        for (int k = 0; k < 10; k++) {
            int i = k * THREADS + tid;
            int r = i / 20, c = i - r * 20;
            *(uint4*)(sm + OFF_X + r * ROWB + c * 16) =
                *(const uint4*)(xg + (size_t)r * 320 + c * 16);
        }
    }
    if (tid < 128) ((float*)(sm + OFF_X2S))[tid] = g_x2[m_tile * 128 + tid];
    {   // Mt rows 10..15 (ones column for den, zeros) into BOTH buffers
        __half one = __float2half(1.0f);
        __half zro = __float2half(0.0f);
        for (int i = tid; i < 6 * TN; i += THREADS) {
            int c = 10 + i / TN, j = i - (c - 10) * TN;
            __half v = (c == 10) ? one : zro;
            *(__half*)(sm + OFF_MT0 + c * MTROWB + j * 2) = v;
            *(__half*)(sm + OFF_MT1 + c * MTROWB + j * 2) = v;
        }
    }
    __syncthreads();

    const int lrow = (lane & 7) + ((lane >> 3) & 1) * 8;
    const int lcol = ((lane >> 4) & 1) * 16;
    uint32_t aA[2];
    #pragma unroll
    for (int mf = 0; mf < 2; mf++)
        aA[mf] = sb + OFF_X + (mw * 32 + mf * 16 + lrow) * ROWB + lcol;
    uint32_t bBo[2];
    #pragma unroll
    for (int p = 0; p < 2; p++)
        bBo[p] = (uint32_t)((nw * 32 + p * 16 + lrow) * ROWB + lcol);

    float x2a[4];
    {
        const float* x2s = (const float*)(sm + OFF_X2S);
        #pragma unroll
        for (int q = 0; q < 4; q++)
            x2a[q] = x2s[mw * 32 + (q >> 1) * 16 + (q & 1) * 8 + g];
    }

    float acc2[2][2][4];
    #pragma unroll
    for (int mf = 0; mf < 2; mf++)
        #pragma unroll
        for (int n = 0; n < 2; n++)
            #pragma unroll
            for (int q = 0; q < 4; q++) acc2[mf][n][q] = 0.f;
    float accA[2][4][4], accB[2][4][4];

    // --- pipelined tile loop --------------------------------------------
    tile_body<false>(0, a_start, tid, nw, tig, lrow, lcol, sb, sm,
                     aA, bBo, x2a, accA, accB, acc2, Mv);
    #pragma unroll 1
    for (int tp = 0; tp < 7; tp++) {
        tile_body<true>(2 * tp + 1, a_start, tid, nw, tig, lrow, lcol, sb, sm,
                        aA, bBo, x2a, accB, accA, acc2, Mv);
        tile_body<true>(2 * tp + 2, a_start, tid, nw, tig, lrow, lcol, sb, sm,
                        aA, bBo, x2a, accA, accB, acc2, Mv);
    }
    tile_body<true>(15, a_start, tid, nw, tig, lrow, lcol, sb, sm,
                    aA, bBo, x2a, accB, accA, acc2, Mv);

    // --- drain: epilogue for tile 15 (in accB, buffers parity 1) --------
    __syncthreads();
    {
        const int po = 1;
        const uint32_t bMb = sb + OFF_MT0 + po * SZ_MTBUF + lrow * MTROWB + lcol;
        const char* y2s = sm + OFF_Y2S0 + po * 256;
        uint32_t bm[4];
        float2 lo, hi;
        LDMX4(bm, bMb + (nw * 32) * 2);
        lo = *(const float2*)(y2s + (nw * 32 + tig * 2) * 4);
        hi = *(const float2*)(y2s + (nw * 32 + 8 + tig * 2) * 4);
        epi_piece(0, 0, accB, acc2, x2a, bm, lo, hi);
        epi_piece(0, 1, accB, acc2, x2a, bm, lo, hi);
        LDMX4(bm, bMb + (nw * 32 + 16) * 2);
        lo = *(const float2*)(y2s + (nw * 32 + 16 + tig * 2) * 4);
        hi = *(const float2*)(y2s + (nw * 32 + 24 + tig * 2) * 4);
        epi_piece(1, 0, accB, acc2, x2a, bm, lo, hi);
        epi_piece(1, 1, accB, acc2, x2a, bm, lo, hi);
    }

    // --- reduce nw halves via smem, write per-split partials -------------
    __syncthreads();
    float* red = (float*)(sm + OFF_Y0);    // scratch [4 mw][32 lane][16]
    if (nw == 1) {
        float* d = red + (mw * 32 + lane) * 16;
        #pragma unroll
        for (int mf = 0; mf < 2; mf++)
            #pragma unroll
            for (int n = 0; n < 2; n++)
                #pragma unroll
                for (int q = 0; q < 4; q++)
                    d[mf * 8 + n * 4 + q] = acc2[mf][n][q];
    }
    __syncthreads();
    if (nw == 0) {
        const float* s = red + (mw * 32 + lane) * 16;
        #pragma unroll
        for (int mf = 0; mf < 2; mf++) {
            int r0 = m_tile * 128 + mw * 32 + mf * 16 + g;
            size_t base = ((size_t)split * NQ + r0) * 16 + tig * 2;
            #pragma unroll
            for (int n = 0; n < 2; n++) {
                *(float2*)&g_part[base + n * 8] = make_float2(
                    acc2[mf][n][0] + s[mf * 8 + n * 4 + 0],
                    acc2[mf][n][1] + s[mf * 8 + n * 4 + 1]);
                *(float2*)&g_part[base + 8 * 16 + n * 8] = make_float2(
                    acc2[mf][n][2] + s[mf * 8 + n * 4 + 2],
                    acc2[mf][n][3] + s[mf * 8 + n * 4 + 3]);
            }
        }
    }
}

// ---------------------------------------------------------------------------
// Kernel 2: combine splits, normalize
// ---------------------------------------------------------------------------
__global__ void combine_kernel(float* __restrict__ out) {
    __shared__ float dsh[16];
    int tid = threadIdx.x;
    int il = tid >> 4, c = tid & 15;
    int i = blockIdx.x * 16 + il;
    float s = 0.f;
    #pragma unroll 4
    for (int sp = 0; sp < SPLITS; sp++)
        s += g_part[((size_t)sp * NQ + i) * 16 + c];
    if (c == 10) dsh[il] = s;
    __syncthreads();
    if (c < 10) out[(size_t)i * NC + c] = s / dsh[il];
}

// ---------------------------------------------------------------------------
// kernel_launch
// ---------------------------------------------------------------------------
extern "C" void kernel_launch(void* const* d_in, const int* in_sizes, int n_in,
                              void* d_out, int out_size) {
    const float* X  = (const float*)d_in[0];   // inputs  [4096, 160]
    const float* Y  = (const float*)d_in[1];   // Address [32768, 160]
    const float* Mv = (const float*)d_in[2];   // M       [32768, 10]
    float* out = (float*)d_out;                // [4096, 10]

    static bool attr_done = false;
    if (!attr_done) {
        cudaFuncSetAttribute(fused_kernel,
                             cudaFuncAttributeMaxDynamicSharedMemorySize, SMEM_BYTES);
        attr_done = true;
    }

    int norm_warps = NQ + NA;
    norms_kernel<<<(norm_warps * 32 + 255) / 256, 256>>>(X, Y);
    fused_kernel<<<(NQ / 128) * SPLITS, THREADS, SMEM_BYTES>>>(Mv);
    combine_kernel<<<NQ / 16, 256>>>(out);
}

// round 13
// speedup vs baseline: 1.0208x; 1.0208x over previous
#include <cuda_runtime.h>
#include <cuda_fp16.h>
#include <cstdint>

// ---------------------------------------------------------------------------
// Problem constants
// ---------------------------------------------------------------------------
#define THREADS 256
#define F_DIM 160
#define NQ 4096
#define NA 32768
#define NC 10
#define SPLITS 32
#define A_CHUNK 1024          // addresses per CTA
#define TN 64                 // N tile (addresses per tile)
#define NTILES (A_CHUNK / TN) // 16
#define KEXP (-1.31154095f)   // -log2(e)/1.1 : exp(-d/1.1) = 2^(d*KEXP)
#define WSHIFT 24.0f          // softmin-invariant weight scale 2^24
#define TCLAMP 14.0f          // clamp t -> w <= 2^14 (fp16-safe)

// ---------------------------------------------------------------------------
// Shared memory layout (fp16 tiles, 336B rows -> conflict-free ldmatrix).
// Mt / y2 double-buffered (published one tile ahead).
// ---------------------------------------------------------------------------
#define ROWB 336
#define MTROWB 144
#define OFF_X    0
#define SZ_X     (128 * ROWB)            // 43008
#define OFF_Y0   SZ_X                    // 43008
#define SZ_YBUF  (TN * ROWB)             // 21504
#define OFF_Y1   (OFF_Y0 + SZ_YBUF)      // 64512
#define OFF_MT0  (OFF_Y1 + SZ_YBUF)      // 86016
#define SZ_MTBUF (16 * MTROWB)           // 2304
#define OFF_MT1  (OFF_MT0 + SZ_MTBUF)    // 88320
#define OFF_Y2S0 (OFF_MT1 + SZ_MTBUF)    // 90624
#define OFF_Y2S1 (OFF_Y2S0 + 256)        // 90880
#define OFF_X2S  (OFF_Y2S1 + 256)        // 91136
#define SMEM_BYTES (OFF_X2S + 512)       // 91648 (x2 CTAs = 183KB/SM, fits)

// ---------------------------------------------------------------------------
// Device scratch
// ---------------------------------------------------------------------------
__device__ __half g_xh[(size_t)NQ * F_DIM];
__device__ __half g_yh[(size_t)NA * F_DIM];
__device__ float g_x2[NQ];
__device__ float g_y2[NA];
__device__ float g_part[(size_t)SPLITS * NQ * 16];  // [split][row][16]: 10 num, den@10

// ---------------------------------------------------------------------------
// PTX helpers
// ---------------------------------------------------------------------------
__device__ __forceinline__ uint32_t cvta_s(const void* p) {
    uint32_t r;
    asm("{ .reg .u64 t; cvta.to.shared.u64 t, %1; cvt.u32.u64 %0, t; }"
        : "=r"(r) : "l"(p));
    return r;
}

#define LDMX4(r, a)                                                            \
    asm volatile("ldmatrix.sync.aligned.m8n8.x4.shared.b16 {%0,%1,%2,%3}, [%4];" \
                 : "=r"((r)[0]), "=r"((r)[1]), "=r"((r)[2]), "=r"((r)[3])      \
                 : "r"(a))

#define MMA_F16(d, a, b0, b1)                                                  \
    asm volatile("mma.sync.aligned.m16n8k16.row.col.f32.f16.f16.f32 "          \
                 "{%0,%1,%2,%3},{%4,%5,%6,%7},{%8,%9},{%0,%1,%2,%3};"          \
                 : "+f"((d)[0]), "+f"((d)[1]), "+f"((d)[2]), "+f"((d)[3])      \
                 : "r"((a)[0]), "r"((a)[1]), "r"((a)[2]), "r"((a)[3]),         \
                   "r"(b0), "r"(b1))

#define CPASYNC16(d, s)                                                        \
    asm volatile("cp.async.cg.shared.global [%0], [%1], 16;" :: "r"(d), "l"(s))
#define CPCOMMIT() asm volatile("cp.async.commit_group;" ::: "memory")
#define CPWAIT1()  asm volatile("cp.async.wait_group 1;" ::: "memory")

// issue cp.async for one Y tile (fp16): rows [a0row, a0row+64), 320B/row
__device__ __forceinline__ void issue_y(int a0row, uint32_t dbase, int tid) {
    const char* gs = (const char*)(g_yh + (size_t)a0row * F_DIM);
    #pragma unroll
    for (int k = 0; k < 5; k++) {
        int i = k * THREADS + tid;        // 64 rows x 20 x 16B
        int r = i / 20, c = i - r * 20;
        CPASYNC16(dbase + r * ROWB + c * 16, gs + (size_t)r * 320 + c * 16);
    }
}

// two f32 scores -> fp16x2 softmin-weight pair (one GEMM-2 A-fragment reg)
__device__ __forceinline__ uint32_t wpair2(float s0, float s1, float x2v, float2 y2) {
    float d20 = fmaxf(fmaf(-2.f, s0, x2v + y2.x), 0.f);
    float d21 = fmaxf(fmaf(-2.f, s1, x2v + y2.y), 0.f);
    float d0, d1;
    asm("sqrt.approx.ftz.f32 %0, %1;" : "=f"(d0) : "f"(d20));
    asm("sqrt.approx.ftz.f32 %0, %1;" : "=f"(d1) : "f"(d21));
    float t0 = fminf(fmaf(KEXP, d0, WSHIFT), TCLAMP);
    float t1 = fminf(fmaf(KEXP, d1, WSHIFT), TCLAMP);
    __half2 th = __floats2half2_rn(t0, t1);
    uint32_t w;
    asm("ex2.approx.f16x2 %0, %1;" : "=r"(w) : "r"(*(uint32_t*)&th));
    return w;
}

// epilogue for one mf of a 16-col half-tile accumulator: weights -> GEMM-2
__device__ __forceinline__ void epi_half(
    int mf, const float (&accP)[2][2][4], float (&acc2)[2][2][4],
    const float (&x2a)[4], const uint32_t* bm, float2 y2lo, float2 y2hi)
{
    uint32_t af[4];
    af[0] = wpair2(accP[mf][0][0], accP[mf][0][1], x2a[mf * 2],     y2lo);
    af[1] = wpair2(accP[mf][0][2], accP[mf][0][3], x2a[mf * 2 + 1], y2lo);
    af[2] = wpair2(accP[mf][1][0], accP[mf][1][1], x2a[mf * 2],     y2hi);
    af[3] = wpair2(accP[mf][1][2], accP[mf][1][3], x2a[mf * 2 + 1], y2hi);
    MMA_F16(acc2[mf][0], af, bm[0], bm[2]);
    MMA_F16(acc2[mf][1], af, bm[1], bm[3]);
}

// ---------------------------------------------------------------------------
// One GEMM-1 N-half phase (10 K-steps into accP), with the epilogue of accE
// (the previously finished half) interleaved between K-steps.
// ---------------------------------------------------------------------------
template<bool DO_EPI>
__device__ __forceinline__ void gemm1_phase(
    uint32_t yB, const uint32_t (&aA)[2], uint32_t bBoP,
    float (&accP)[2][2][4], const float (&accE)[2][2][4],
    float (&acc2)[2][2][4], const float (&x2a)[4],
    uint32_t bMbE, const char* y2sE, int cbaseE, int tig)
{
    #pragma unroll
    for (int mf = 0; mf < 2; mf++)
        #pragma unroll
        for (int hi = 0; hi < 2; hi++)
            #pragma unroll
            for (int q = 0; q < 4; q++) accP[mf][hi][q] = 0.f;
    uint32_t bm[4];
    float2 y2lo, y2hi;
    #pragma unroll
    for (int ks = 0; ks < 10; ks++) {
        uint32_t afr[2][4], bfr[4];
        LDMX4(afr[0], aA[0] + ks * 32);
        LDMX4(afr[1], aA[1] + ks * 32);
        LDMX4(bfr, yB + bBoP + ks * 32);
        #pragma unroll
        for (int mf = 0; mf < 2; mf++) {
            MMA_F16(accP[mf][0], afr[mf], bfr[0], bfr[2]);
            MMA_F16(accP[mf][1], afr[mf], bfr[1], bfr[3]);
        }
        if (DO_EPI) {
            if (ks == 1) {
                LDMX4(bm, bMbE + cbaseE * 2);
                y2lo = *(const float2*)(y2sE + (cbaseE + tig * 2) * 4);
                y2hi = *(const float2*)(y2sE + (cbaseE + 8 + tig * 2) * 4);
            }
            if (ks == 3) epi_half(0, accE, acc2, x2a, bm, y2lo, y2hi);
            if (ks == 6) epi_half(1, accE, acc2, x2a, bm, y2lo, y2hi);
        }
    }
}

// ---------------------------------------------------------------------------
// Kernel 0: exact fp32 row norms + fp16 conversion
// ---------------------------------------------------------------------------
__global__ void norms_kernel(const float* __restrict__ X, const float* __restrict__ Y) {
    int gw = (int)((blockIdx.x * blockDim.x + threadIdx.x) >> 5);
    int lane = threadIdx.x & 31;
    const float4* src;
    uint2* dsth;
    float* dst;
    if (gw < NQ) {
        src = (const float4*)(X + (size_t)gw * F_DIM);
        dsth = (uint2*)(g_xh + (size_t)gw * F_DIM); dst = g_x2 + gw;
    } else if (gw < NQ + NA) {
        int r = gw - NQ;
        src = (const float4*)(Y + (size_t)r * F_DIM);
        dsth = (uint2*)(g_yh + (size_t)r * F_DIM); dst = g_y2 + r;
    } else return;
    float s = 0.f;
    #pragma unroll
    for (int k = 0; k < 2; k++) {
        int j = lane + k * 32;
        if (k == 0 || j < 40) {
            float4 v = src[j];
            s = fmaf(v.x, v.x, s); s = fmaf(v.y, v.y, s);
            s = fmaf(v.z, v.z, s); s = fmaf(v.w, v.w, s);
            __half2 h0 = __floats2half2_rn(v.x, v.y);
            __half2 h1 = __floats2half2_rn(v.z, v.w);
            uint2 u;
            u.x = *(uint32_t*)&h0; u.y = *(uint32_t*)&h1;
            dsth[j] = u;
        }
    }
    #pragma unroll
    for (int o = 16; o > 0; o >>= 1) s += __shfl_xor_sync(0xFFFFFFFFu, s, o);
    if (lane == 0) *dst = s;
}

// ---------------------------------------------------------------------------
// Kernel 1: fused, N-half phase-pipelined. 2 CTAs/SM, 256 threads.
// ---------------------------------------------------------------------------
__global__ void __launch_bounds__(THREADS, 2) fused_kernel(
    const float* __restrict__ Mv)
{
    extern __shared__ __align__(1024) char sm[];
    const uint32_t sb = cvta_s(sm);
    const int tid  = threadIdx.x;
    const int lane = tid & 31, warp = tid >> 5;
    const int mw = warp >> 1, nw = warp & 1;
    const int g = lane >> 2, tig = lane & 3;
    const int m_tile = (int)blockIdx.x >> 5;
    const int split  = (int)blockIdx.x & (SPLITS - 1);
    const int a_start = split * A_CHUNK;

    // --- prologue -------------------------------------------------------
    issue_y(a_start, sb + OFF_Y0, tid); CPCOMMIT();
    issue_y(a_start + TN, sb + OFF_Y1, tid); CPCOMMIT();
    {
        const char* xg = (const char*)(g_xh + (size_t)m_tile * 128 * F_DIM);
        #pragma unroll
        for (int k = 0; k < 10; k++) {
            int i = k * THREADS + tid;
            int r = i / 20, c = i - r * 20;
            *(uint4*)(sm + OFF_X + r * ROWB + c * 16) =
                *(const uint4*)(xg + (size_t)r * 320 + c * 16);
        }
    }
    if (tid < 128) ((float*)(sm + OFF_X2S))[tid] = g_x2[m_tile * 128 + tid];
    {   // Mt rows 10..15 (ones column for den, zeros) into BOTH buffers
        __half one = __float2half(1.0f);
        __half zro = __float2half(0.0f);
        for (int i = tid; i < 6 * TN; i += THREADS) {
            int c = 10 + i / TN, j = i - (c - 10) * TN;
            __half v = (c == 10) ? one : zro;
            *(__half*)(sm + OFF_MT0 + c * MTROWB + j * 2) = v;
            *(__half*)(sm + OFF_MT1 + c * MTROWB + j * 2) = v;
        }
    }
    {   // publish Mt(0) + y2(0) into buffer 0 directly
        for (int i = tid; i < TN * NC; i += THREADS) {
            int j = i / 10, c = i - j * 10;
            *(__half*)(sm + OFF_MT0 + c * MTROWB + j * 2) =
                __float2half_rn(Mv[(size_t)(a_start + j) * NC + c]);
        }
        if (tid < TN) ((float*)(sm + OFF_Y2S0))[tid] = g_y2[a_start + tid];
    }
    __syncthreads();

    const int lrow = (lane & 7) + ((lane >> 3) & 1) * 8;
    const int lcol = ((lane >> 4) & 1) * 16;
    uint32_t aA[2];
    #pragma unroll
    for (int mf = 0; mf < 2; mf++)
        aA[mf] = sb + OFF_X + (mw * 32 + mf * 16 + lrow) * ROWB + lcol;
    uint32_t bBo[2];
    #pragma unroll
    for (int p = 0; p < 2; p++)
        bBo[p] = (uint32_t)((nw * 32 + p * 16 + lrow) * ROWB + lcol);

    float x2a[4];
    {
        const float* x2s = (const float*)(sm + OFF_X2S);
        #pragma unroll
        for (int q = 0; q < 4; q++)
            x2a[q] = x2s[mw * 32 + (q >> 1) * 16 + (q & 1) * 8 + g];
    }

    float acc2[2][2][4];
    #pragma unroll
    for (int mf = 0; mf < 2; mf++)
        #pragma unroll
        for (int n = 0; n < 2; n++)
            #pragma unroll
            for (int q = 0; q < 4; q++) acc2[mf][n][q] = 0.f;
    float accP0[2][2][4], accP1[2][2][4];

    // --- tile loop --------------------------------------------------------
    #pragma unroll 1
    for (int t = 0; t < NTILES; t++) {
        // prefetch Mt(t+1) + y2(t+1) into registers
        float mv[3];
        float y2v = 0.f;
        if (t + 1 < NTILES) {
            #pragma unroll
            for (int k = 0; k < 3; k++) {
                int i = k * THREADS + tid;
                if (i < TN * NC) {
                    int j = i / 10, c = i - j * 10;
                    mv[k] = Mv[(size_t)(a_start + (t + 1) * TN + j) * NC + c];
                }
            }
            if (tid < TN) y2v = g_y2[a_start + (t + 1) * TN + tid];
        }

        CPWAIT1();              // Y buffer [t&1] complete
        __syncthreads();        // S1: Y + Mt(t) visible; prev epi done

        const uint32_t yB = sb + OFF_Y0 + (t & 1) * SZ_YBUF;
        const int pA = (t - 1) & 1;    // Mt/y2 parity for epi of tile t-1
        const int pB = t & 1;          // Mt/y2 parity for epi of tile t
        // phase A: build accP0(t); interleave epi(j2=1) of accP1(t-1)
        if (t == 0)
            gemm1_phase<false>(yB, aA, bBo[0], accP0, accP1, acc2, x2a,
                               0u, (const char*)sm, 0, tig);
        else
            gemm1_phase<true>(yB, aA, bBo[0], accP0, accP1, acc2, x2a,
                              sb + OFF_MT0 + pA * SZ_MTBUF + lrow * MTROWB + lcol,
                              sm + OFF_Y2S0 + pA * 256, nw * 32 + 16, tig);
        // phase B: build accP1(t); interleave epi(j2=0) of accP0(t)
        gemm1_phase<true>(yB, aA, bBo[1], accP1, accP0, acc2, x2a,
                          sb + OFF_MT0 + pB * SZ_MTBUF + lrow * MTROWB + lcol,
                          sm + OFF_Y2S0 + pB * 256, nw * 32, tig);

        __syncthreads();        // S2: Y[t&1] and Mt[pA] free
        if (t + 2 < NTILES)
            issue_y(a_start + (t + 2) * TN, sb + OFF_Y0 + (t & 1) * SZ_YBUF, tid);
        CPCOMMIT();
        if (t + 1 < NTILES) {   // publish Mt(t+1)/y2(t+1) into buf (t+1)&1
            char* mtb = sm + OFF_MT0 + ((t + 1) & 1) * SZ_MTBUF;
            #pragma unroll
            for (int k = 0; k < 3; k++) {
                int i = k * THREADS + tid;
                if (i < TN * NC) {
                    int j = i / 10, c = i - j * 10;
                    *(__half*)(mtb + c * MTROWB + j * 2) = __float2half_rn(mv[k]);
                }
            }
            if (tid < TN)
                *((float*)(sm + OFF_Y2S0 + ((t + 1) & 1) * 256) + tid) = y2v;
        }
    }

    // --- drain: epilogue (j2=1) of accP1(15), buffers parity 1 -----------
    {
        const uint32_t bMbE = sb + OFF_MT0 + 1 * SZ_MTBUF + lrow * MTROWB + lcol;
        const char* y2sE = sm + OFF_Y2S0 + 1 * 256;
        const int cbase = nw * 32 + 16;
        uint32_t bm[4];
        LDMX4(bm, bMbE + cbase * 2);
        float2 lo = *(const float2*)(y2sE + (cbase + tig * 2) * 4);
        float2 hi = *(const float2*)(y2sE + (cbase + 8 + tig * 2) * 4);
        epi_half(0, accP1, acc2, x2a, bm, lo, hi);
        epi_half(1, accP1, acc2, x2a, bm, lo, hi);
    }

    // --- reduce nw halves via smem, write per-split partials -------------
    __syncthreads();
    float* red = (float*)(sm + OFF_Y0);    // scratch [4 mw][32 lane][16]
    if (nw == 1) {
        float* d = red + (mw * 32 + lane) * 16;
        #pragma unroll
        for (int mf = 0; mf < 2; mf++)
            #pragma unroll
            for (int n = 0; n < 2; n++)
                #pragma unroll
                for (int q = 0; q < 4; q++)
                    d[mf * 8 + n * 4 + q] = acc2[mf][n][q];
    }
    __syncthreads();
    if (nw == 0) {
        const float* s = red + (mw * 32 + lane) * 16;
        #pragma unroll
        for (int mf = 0; mf < 2; mf++) {
            int r0 = m_tile * 128 + mw * 32 + mf * 16 + g;
            size_t base = ((size_t)split * NQ + r0) * 16 + tig * 2;
            #pragma unroll
            for (int n = 0; n < 2; n++) {
                *(float2*)&g_part[base + n * 8] = make_float2(
                    acc2[mf][n][0] + s[mf * 8 + n * 4 + 0],
                    acc2[mf][n][1] + s[mf * 8 + n * 4 + 1]);
                *(float2*)&g_part[base + 8 * 16 + n * 8] = make_float2(
                    acc2[mf][n][2] + s[mf * 8 + n * 4 + 2],
                    acc2[mf][n][3] + s[mf * 8 + n * 4 + 3]);
            }
        }
    }
}

// ---------------------------------------------------------------------------
// Kernel 2: combine splits, normalize
// ---------------------------------------------------------------------------
__global__ void combine_kernel(float* __restrict__ out) {
    __shared__ float dsh[16];
    int tid = threadIdx.x;
    int il = tid >> 4, c = tid & 15;
    int i = blockIdx.x * 16 + il;
    float s = 0.f;
    #pragma unroll 4
    for (int sp = 0; sp < SPLITS; sp++)
        s += g_part[((size_t)sp * NQ + i) * 16 + c];
    if (c == 10) dsh[il] = s;
    __syncthreads();
    if (c < 10) out[(size_t)i * NC + c] = s / dsh[il];
}

// ---------------------------------------------------------------------------
// kernel_launch
// ---------------------------------------------------------------------------
extern "C" void kernel_launch(void* const* d_in, const int* in_sizes, int n_in,
                              void* d_out, int out_size) {
    const float* X  = (const float*)d_in[0];   // inputs  [4096, 160]
    const float* Y  = (const float*)d_in[1];   // Address [32768, 160]
    const float* Mv = (const float*)d_in[2];   // M       [32768, 10]
    float* out = (float*)d_out;                // [4096, 10]

    static bool attr_done = false;
    if (!attr_done) {
        cudaFuncSetAttribute(fused_kernel,
                             cudaFuncAttributeMaxDynamicSharedMemorySize, SMEM_BYTES);
        attr_done = true;
    }

    int norm_warps = NQ + NA;
    norms_kernel<<<(norm_warps * 32 + 255) / 256, 256>>>(X, Y);
    fused_kernel<<<(NQ / 128) * SPLITS, THREADS, SMEM_BYTES>>>(Mv);
    combine_kernel<<<NQ / 16, 256>>>(out);
}